// round 1
// baseline (speedup 1.0000x reference)
#include <cuda_runtime.h>
#include <cstdint>

#define B_  4
#define M_  65536
#define N_  16384
#define CP_ 64
#define CC_ 128
#define D_  128

// 32 MB scratch for Z = w_cur^T @ cur_x, laid out [b][n][d] so the per-token
// gather is 512 contiguous bytes (L2-resident).
__device__ float g_Z[(size_t)B_ * N_ * D_];
__device__ int g_idx_is64;

// ---------- packed f32x2 helpers (FFMA2 path, sm_103a) ----------
__device__ __forceinline__ unsigned long long splat2(float v) {
    unsigned long long r;
    asm("mov.b64 %0, {%1, %2};" : "=l"(r) : "f"(v), "f"(v));
    return r;
}
__device__ __forceinline__ void fma2(unsigned long long& d,
                                     unsigned long long a,
                                     unsigned long long b) {
    asm("fma.rn.f32x2 %0, %1, %2, %0;" : "+l"(d) : "l"(a), "l"(b));
}
__device__ __forceinline__ float2 unpack2(unsigned long long v) {
    float2 f;
    asm("mov.b64 {%0, %1}, %2;" : "=f"(f.x), "=f"(f.y) : "l"(v));
    return f;
}

// ---------- idx dtype detection (int64 vs int32) ----------
// If the buffer is really int32, an int64 view combines pairs -> values >= 2^32
// unless the odd element is 0 (p = 1/16384 each). 64 probes make misdetection
// probability ~0. Reads only 512B, safe for either layout.
__global__ void detect_idx_kernel(const void* idx) {
    const long long* p = (const long long*)idx;
    int ok = 1;
    for (int i = 0; i < 64; i++) {
        long long v = p[i];
        if (v < 0 || v >= N_) { ok = 0; break; }
    }
    g_idx_is64 = ok;
}

// =====================================================================
// Kernel A: Z[b][n][d] = sum_c cur_x[b][c][n] * w[CP_+c][d]
// Tile: 64 n x 128 d per block, K=128 in two 64-chunks. 256 threads.
// Thread tile: 4 n x 8 d, d packed as 4 f32x2 accumulIn pairs.
// =====================================================================
__global__ __launch_bounds__(256) void zgemm_kernel(const float* __restrict__ cur_x,
                                                    const float* __restrict__ w) {
    __shared__ float sA[64 * 64];    // [k][n]
    __shared__ float sW[64 * 128];   // [k][d]

    const int tid = threadIdx.x;
    const int bb  = blockIdx.y;
    const int n0  = blockIdx.x * 64;
    const int td  = tid & 15;        // d-group: 8 d each
    const int tg  = tid >> 4;        // n-group: 4 n each

    unsigned long long acc[4][4];
#pragma unroll
    for (int i = 0; i < 4; i++)
#pragma unroll
        for (int j = 0; j < 4; j++) acc[i][j] = 0ull;

    const float* curb = cur_x + (size_t)bb * CC_ * N_;

    for (int k0 = 0; k0 < CC_; k0 += 64) {
        // load cur tile 64k x 64n (coalesced: n contiguous)
#pragma unroll
        for (int i = 0; i < 4; i++) {
            int li = tid + i * 256;
            int kk = li >> 4, nn = (li & 15) << 2;
            *(float4*)&sA[kk * 64 + nn] =
                *(const float4*)&curb[(size_t)(k0 + kk) * N_ + n0 + nn];
        }
        // load w_cur chunk 64k x 128d
#pragma unroll
        for (int i = 0; i < 8; i++) {
            int li = tid + i * 256;
            int kk = li >> 5, dd = (li & 31) << 2;
            *(float4*)&sW[kk * 128 + dd] =
                *(const float4*)&w[(size_t)(CP_ + k0 + kk) * D_ + dd];
        }
        __syncthreads();

#pragma unroll 16
        for (int kk = 0; kk < 64; kk++) {
            float4 av = *(const float4*)&sA[kk * 64 + tg * 4];
            const ulonglong2* wp = (const ulonglong2*)&sW[kk * 128 + td * 8];
            ulonglong2 w01 = wp[0];
            ulonglong2 w23 = wp[1];
            unsigned long long a0 = splat2(av.x), a1 = splat2(av.y);
            unsigned long long a2 = splat2(av.z), a3 = splat2(av.w);
            fma2(acc[0][0], a0, w01.x); fma2(acc[0][1], a0, w01.y);
            fma2(acc[0][2], a0, w23.x); fma2(acc[0][3], a0, w23.y);
            fma2(acc[1][0], a1, w01.x); fma2(acc[1][1], a1, w01.y);
            fma2(acc[1][2], a1, w23.x); fma2(acc[1][3], a1, w23.y);
            fma2(acc[2][0], a2, w01.x); fma2(acc[2][1], a2, w01.y);
            fma2(acc[2][2], a2, w23.x); fma2(acc[2][3], a2, w23.y);
            fma2(acc[3][0], a3, w01.x); fma2(acc[3][1], a3, w01.y);
            fma2(acc[3][2], a3, w23.x); fma2(acc[3][3], a3, w23.y);
        }
        __syncthreads();
    }

    // store Z (packed pairs are memory-layout compatible: lo = first float)
#pragma unroll
    for (int i = 0; i < 4; i++) {
        size_t off = ((size_t)bb * N_ + n0 + tg * 4 + i) * D_ + td * 8;
        *(ulonglong2*)&g_Z[off]     = make_ulonglong2(acc[i][0], acc[i][1]);
        *(ulonglong2*)&g_Z[off + 4] = make_ulonglong2(acc[i][2], acc[i][3]);
    }
}

// =====================================================================
// Kernel B: out[b][m][d] = relu((pre_x[b,:,m] @ w_pre + Z[b,idx[b,m],:]) * s + t)
// Tile: 64 m x 128 d per block, K=64. 256 threads, thread tile 4 m x 8 d.
// =====================================================================
__global__ __launch_bounds__(256) void fuse_kernel(const float* __restrict__ pre_x,
                                                   const void*  __restrict__ up_idx,
                                                   const float* __restrict__ w,
                                                   const float* __restrict__ bias,
                                                   const float* __restrict__ gamma,
                                                   const float* __restrict__ beta,
                                                   const float* __restrict__ rmean,
                                                   const float* __restrict__ rvar,
                                                   float* __restrict__ out) {
    __shared__ float sP[64 * 64];    // [k][m]
    __shared__ float sW[64 * 128];   // [k][d]

    const int tid = threadIdx.x;
    const int bb  = blockIdx.y;
    const int m0  = blockIdx.x * 64;
    const int td  = tid & 15;
    const int tg  = tid >> 4;

    const float* preb = pre_x + (size_t)bb * CP_ * M_;

    // load pre tile 64k x 64m (m contiguous -> coalesced)
#pragma unroll
    for (int i = 0; i < 4; i++) {
        int li = tid + i * 256;
        int kk = li >> 4, mm = (li & 15) << 2;
        *(float4*)&sP[kk * 64 + mm] =
            *(const float4*)&preb[(size_t)kk * M_ + m0 + mm];
    }
    // load w_pre 64k x 128d
#pragma unroll
    for (int i = 0; i < 8; i++) {
        int li = tid + i * 256;
        int kk = li >> 5, dd = (li & 31) << 2;
        *(float4*)&sW[kk * 128 + dd] = *(const float4*)&w[(size_t)kk * D_ + dd];
    }
    __syncthreads();

    unsigned long long acc[4][4];
#pragma unroll
    for (int i = 0; i < 4; i++)
#pragma unroll
        for (int j = 0; j < 4; j++) acc[i][j] = 0ull;

#pragma unroll 16
    for (int kk = 0; kk < 64; kk++) {
        float4 av = *(const float4*)&sP[kk * 64 + tg * 4];
        const ulonglong2* wp = (const ulonglong2*)&sW[kk * 128 + td * 8];
        ulonglong2 w01 = wp[0];
        ulonglong2 w23 = wp[1];
        unsigned long long a0 = splat2(av.x), a1 = splat2(av.y);
        unsigned long long a2 = splat2(av.z), a3 = splat2(av.w);
        fma2(acc[0][0], a0, w01.x); fma2(acc[0][1], a0, w01.y);
        fma2(acc[0][2], a0, w23.x); fma2(acc[0][3], a0, w23.y);
        fma2(acc[1][0], a1, w01.x); fma2(acc[1][1], a1, w01.y);
        fma2(acc[1][2], a1, w23.x); fma2(acc[1][3], a1, w23.y);
        fma2(acc[2][0], a2, w01.x); fma2(acc[2][1], a2, w01.y);
        fma2(acc[2][2], a2, w23.x); fma2(acc[2][3], a2, w23.y);
        fma2(acc[3][0], a3, w01.x); fma2(acc[3][1], a3, w01.y);
        fma2(acc[3][2], a3, w23.x); fma2(acc[3][3], a3, w23.y);
    }

    // per-thread folded BN scale/shift for its 8 d's (arrays are tiny & L1-hot)
    const int d8 = td * 8;
    float s[8], t[8];
#pragma unroll
    for (int j = 0; j < 8; j++) {
        float sc = rsqrtf(rvar[d8 + j] + 1e-5f) * gamma[d8 + j];
        s[j] = sc;
        t[j] = (bias[d8 + j] - rmean[d8 + j]) * sc + beta[d8 + j];
    }

    const int is64 = g_idx_is64;
    const long long* p64 = (const long long*)up_idx;
    const int*       p32 = (const int*)up_idx;

#pragma unroll
    for (int i = 0; i < 4; i++) {
        int m = m0 + tg * 4 + i;
        size_t ipos = (size_t)bb * M_ + m;
        int idxv = is64 ? (int)p64[ipos] : p32[ipos];

        const float* zp = g_Z + ((size_t)bb * N_ + idxv) * D_ + d8;
        float4 z0 = *(const float4*)zp;
        float4 z1 = *(const float4*)(zp + 4);

        float2 p0 = unpack2(acc[i][0]);
        float2 p1 = unpack2(acc[i][1]);
        float2 p2 = unpack2(acc[i][2]);
        float2 p3 = unpack2(acc[i][3]);

        float4 o0, o1;
        o0.x = fmaxf((p0.x + z0.x) * s[0] + t[0], 0.0f);
        o0.y = fmaxf((p0.y + z0.y) * s[1] + t[1], 0.0f);
        o0.z = fmaxf((p1.x + z0.z) * s[2] + t[2], 0.0f);
        o0.w = fmaxf((p1.y + z0.w) * s[3] + t[3], 0.0f);
        o1.x = fmaxf((p2.x + z1.x) * s[4] + t[4], 0.0f);
        o1.y = fmaxf((p2.y + z1.y) * s[5] + t[5], 0.0f);
        o1.z = fmaxf((p3.x + z1.z) * s[6] + t[6], 0.0f);
        o1.w = fmaxf((p3.y + z1.w) * s[7] + t[7], 0.0f);

        size_t off = ((size_t)bb * M_ + m) * D_ + d8;
        *(float4*)&out[off]     = o0;
        *(float4*)&out[off + 4] = o1;
    }
}

extern "C" void kernel_launch(void* const* d_in, const int* in_sizes, int n_in,
                              void* d_out, int out_size) {
    const float* pre_x  = (const float*)d_in[0];
    const float* cur_x  = (const float*)d_in[1];
    const void*  up_idx = d_in[2];
    const float* w      = (const float*)d_in[3];
    const float* bias   = (const float*)d_in[4];
    const float* gamma  = (const float*)d_in[5];
    const float* beta   = (const float*)d_in[6];
    const float* rmean  = (const float*)d_in[7];
    const float* rvar   = (const float*)d_in[8];
    float* out = (float*)d_out;

    detect_idx_kernel<<<1, 1>>>(up_idx);
    zgemm_kernel<<<dim3(N_ / 64, B_), 256>>>(cur_x, w);
    fuse_kernel<<<dim3(M_ / 64, B_), 256>>>(pre_x, up_idx, w, bias, gamma, beta,
                                            rmean, rvar, out);
}

// round 3
// speedup vs baseline: 1.8108x; 1.8108x over previous
#include <cuda_runtime.h>
#include <cuda_bf16.h>
#include <cstdint>

#define B_   4
#define M_   65536
#define N_   16384
#define D_   128
#define CIN  192
#define CP_  64

#define APITCH 144            // w tile row pitch (bytes), 16B aligned, frag banks 4r+q distinct
#define BPITCH 148            // x tile row pitch (bytes), STS banks 20g+5j+kp distinct
#define SWORDS 133            // staging row pitch (words), banks 5d+tok distinct

#define OFF_A   1024
#define ASZ     (128 * APITCH)            // 18432
#define OFF_B   (OFF_A + 2 * ASZ)         // 37888
#define BSZ     (128 * BPITCH)            // 18944
#define SMEM_TOTAL (OFF_B + 2 * BSZ)      // 75776
#define OFF_STAGE 1024                    // reuse of A+B region after mainloop

__device__ float g_Z[(size_t)B_ * N_ * D_];            // 32 MB scratch [b][n][d]
__device__ int g_idx_is64;
__device__ __align__(16) unsigned short g_wh[128 * CIN];  // A = w^T, [d][k] bf16 hi
__device__ __align__(16) unsigned short g_wl[128 * CIN];  // lo

// ---------------- helpers ----------------
static __device__ __forceinline__ uint32_t pack2(__nv_bfloat16 lo, __nv_bfloat16 hi) {
    return ((uint32_t)__bfloat16_as_ushort(hi) << 16) | (uint32_t)__bfloat16_as_ushort(lo);
}
static __device__ __forceinline__ void mma_bf16(float* c, const uint32_t* a,
                                                uint32_t b0, uint32_t b1) {
    asm volatile(
        "mma.sync.aligned.m16n8k16.row.col.f32.bf16.bf16.f32 "
        "{%0,%1,%2,%3}, {%4,%5,%6,%7}, {%8,%9}, {%0,%1,%2,%3};"
        : "+f"(c[0]), "+f"(c[1]), "+f"(c[2]), "+f"(c[3])
        : "r"(a[0]), "r"(a[1]), "r"(a[2]), "r"(a[3]), "r"(b0), "r"(b1));
}

// ---------------- setup: w split + idx dtype probe ----------------
__global__ void setup_kernel(const float* __restrict__ w, const void* __restrict__ idx) {
    if (blockIdx.x == 0 && threadIdx.x == 0) {
        const long long* p = (const long long*)idx;
        int ok = 1;
        for (int i = 0; i < 64; i++) {
            long long v = p[i];
            if (v < 0 || v >= N_) { ok = 0; break; }
        }
        g_idx_is64 = ok;
    }
    int i = blockIdx.x * 256 + threadIdx.x;           // over CIN*128, w is [k][d]
    if (i < CIN * 128) {
        int k = i / 128, d = i % 128;
        float x = w[i];
        __nv_bfloat16 h = __float2bfloat16_rn(x);
        __nv_bfloat16 l = __float2bfloat16_rn(x - __bfloat162float(h));
        g_wh[d * CIN + k] = __bfloat16_as_ushort(h);
        g_wl[d * CIN + k] = __bfloat16_as_ushort(l);
    }
}

// ---------------- cooperative tile loaders ----------------
// w tile: [128 d][64 k] hi+lo from g_w*, k-major rows, pitch APITCH
static __device__ __forceinline__ void load_w(char* smc, int k0, int t) {
    int kg = t & 7;
#pragma unroll
    for (int it = 0; it < 4; it++) {
        int d = (t >> 3) + 32 * it;
        uint4 vh = *(const uint4*)(g_wh + (size_t)d * CIN + k0 + kg * 8);
        uint4 vl = *(const uint4*)(g_wl + (size_t)d * CIN + k0 + kg * 8);
        *(uint4*)(smc + OFF_A + d * APITCH + kg * 16) = vh;
        *(uint4*)(smc + OFF_A + ASZ + d * APITCH + kg * 16) = vl;
    }
}
// x tile: 64 k rows x 128 tok, fp32 -> bf16 hi/lo, stored [tok][k] (transposed)
static __device__ __forceinline__ void load_x(char* smc, const float* __restrict__ src,
                                              size_t stride, int t) {
    int kp = t >> 3;                                  // k-pair 0..31
    const float* r0 = src + (size_t)(2 * kp) * stride;
    const float* r1 = r0 + stride;
#pragma unroll
    for (int it = 0; it < 4; it++) {
        int tokg = (t & 7) + 8 * it;
        float4 v0 = *(const float4*)(r0 + tokg * 4);
        float4 v1 = *(const float4*)(r1 + tokg * 4);
        float x0[4] = {v0.x, v0.y, v0.z, v0.w};
        float x1[4] = {v1.x, v1.y, v1.z, v1.w};
#pragma unroll
        for (int j = 0; j < 4; j++) {
            __nv_bfloat16 h0 = __float2bfloat16_rn(x0[j]);
            __nv_bfloat16 h1 = __float2bfloat16_rn(x1[j]);
            __nv_bfloat16 l0 = __float2bfloat16_rn(x0[j] - __bfloat162float(h0));
            __nv_bfloat16 l1 = __float2bfloat16_rn(x1[j] - __bfloat162float(h1));
            int tok = tokg * 4 + j;
            char* p = smc + OFF_B + tok * BPITCH + kp * 4;
            *(uint32_t*)p = pack2(h0, h1);            // (k even, k odd)
            *(uint32_t*)(p + BSZ) = pack2(l0, l1);
        }
    }
}

// ---------------- mainloop: one K=64 chunk of the 128d x 128tok tile ----------------
static __device__ __forceinline__ void compute_chunk(char* smc, int wm, int wn, int lane,
                                                     float acc[2][8][4]) {
    const int r = lane >> 2, q = lane & 3;
    const char* aB = smc + OFF_A + (wm * 32 + r) * APITCH + q * 4;
    const char* bB = smc + OFF_B + (wn * 64 + r) * BPITCH + q * 4;
#pragma unroll
    for (int ks = 0; ks < 4; ks++) {
        uint32_t ah[2][4], al[2][4];
#pragma unroll
        for (int mt = 0; mt < 2; mt++) {
            const char* a0 = aB + mt * 16 * APITCH + ks * 32;
            ah[mt][0] = *(const uint32_t*)a0;
            ah[mt][1] = *(const uint32_t*)(a0 + 8 * APITCH);
            ah[mt][2] = *(const uint32_t*)(a0 + 16);
            ah[mt][3] = *(const uint32_t*)(a0 + 8 * APITCH + 16);
            const char* a1 = a0 + ASZ;
            al[mt][0] = *(const uint32_t*)a1;
            al[mt][1] = *(const uint32_t*)(a1 + 8 * APITCH);
            al[mt][2] = *(const uint32_t*)(a1 + 16);
            al[mt][3] = *(const uint32_t*)(a1 + 8 * APITCH + 16);
        }
#pragma unroll
        for (int nt = 0; nt < 8; nt++) {
            const char* b0 = bB + nt * 8 * BPITCH + ks * 32;
            uint32_t bh0 = *(const uint32_t*)b0;
            uint32_t bh1 = *(const uint32_t*)(b0 + 16);
            uint32_t bl0 = *(const uint32_t*)(b0 + BSZ);
            uint32_t bl1 = *(const uint32_t*)(b0 + BSZ + 16);
#pragma unroll
            for (int mt = 0; mt < 2; mt++) {
                mma_bf16(acc[mt][nt], ah[mt], bh0, bh1);   // hi*hi
                mma_bf16(acc[mt][nt], ah[mt], bl0, bl1);   // hi*lo
                mma_bf16(acc[mt][nt], al[mt], bh0, bh1);   // lo*hi
            }
        }
    }
}

// write accumulators to smem stage [d][tok], pitch SWORDS
static __device__ __forceinline__ void stage_acc(char* smc, int wm, int wn, int lane,
                                                 float acc[2][8][4]) {
    float* stg = (float*)(smc + OFF_STAGE);
    const int r = lane >> 2, q2 = (lane & 3) * 2;
#pragma unroll
    for (int mt = 0; mt < 2; mt++)
#pragma unroll
        for (int nt = 0; nt < 8; nt++) {
            int d0 = wm * 32 + mt * 16 + r;
            int tk = wn * 64 + nt * 8 + q2;
            stg[d0 * SWORDS + tk]       = acc[mt][nt][0];
            stg[d0 * SWORDS + tk + 1]   = acc[mt][nt][1];
            stg[(d0 + 8) * SWORDS + tk]     = acc[mt][nt][2];
            stg[(d0 + 8) * SWORDS + tk + 1] = acc[mt][nt][3];
        }
}

// ---------------- GEMM 1: Z = w_cur^T @ cur_x ----------------
__global__ void __launch_bounds__(256, 2) zgemm(const float* __restrict__ cur) {
    extern __shared__ char smc[];
    const int t = threadIdx.x, lane = t & 31, wid = t >> 5;
    const int wm = wid & 3, wn = wid >> 2;
    const int bb = blockIdx.y, tok0 = blockIdx.x * 128;

    float acc[2][8][4];
#pragma unroll
    for (int a = 0; a < 2; a++)
#pragma unroll
        for (int b = 0; b < 8; b++)
#pragma unroll
            for (int c = 0; c < 4; c++) acc[a][b][c] = 0.0f;

    const float* base = cur + (size_t)bb * 128 * N_ + tok0;
#pragma unroll
    for (int c = 0; c < 2; c++) {
        load_w(smc, CP_ + c * 64, t);
        load_x(smc, base + (size_t)c * 64 * N_, N_, t);
        __syncthreads();
        compute_chunk(smc, wm, wn, lane, acc);
        __syncthreads();
    }
    stage_acc(smc, wm, wn, lane, acc);
    __syncthreads();

    // coalesced store to g_Z[tok][d]
    const float* stg = (const float*)(smc + OFF_STAGE);
    float* zb = g_Z + ((size_t)bb * N_ + tok0) * D_;
    const int g = t & 7, tokl = t >> 3;
#pragma unroll
    for (int p = 0; p < 4; p++) {
        int tok = p * 32 + tokl;
#pragma unroll
        for (int i = 0; i < 4; i++) {
            int d0 = g * 4 + 32 * i;
            float4 v;
            v.x = stg[(d0 + 0) * SWORDS + tok];
            v.y = stg[(d0 + 1) * SWORDS + tok];
            v.z = stg[(d0 + 2) * SWORDS + tok];
            v.w = stg[(d0 + 3) * SWORDS + tok];
            *(float4*)(zb + (size_t)tok * D_ + d0) = v;
        }
    }
}

// ---------------- GEMM 2 + gather + BN + relu ----------------
__global__ void __launch_bounds__(256, 2) fuse(const float* __restrict__ pre,
                                               const void* __restrict__ up_idx,
                                               const float* __restrict__ bias,
                                               const float* __restrict__ gamma,
                                               const float* __restrict__ beta,
                                               const float* __restrict__ rmean,
                                               const float* __restrict__ rvar,
                                               float* __restrict__ out) {
    extern __shared__ char smc[];
    const int t = threadIdx.x, lane = t & 31, wid = t >> 5;
    const int wm = wid & 3, wn = wid >> 2;
    const int bb = blockIdx.y, tok0 = blockIdx.x * 128;

    int* sIdx = (int*)smc;                            // [0,512) — survives staging
    if (t < 128) {
        size_t ip = (size_t)bb * M_ + tok0 + t;
        sIdx[t] = g_idx_is64 ? (int)((const long long*)up_idx)[ip]
                             : ((const int*)up_idx)[ip];
    }

    float acc[2][8][4];
#pragma unroll
    for (int a = 0; a < 2; a++)
#pragma unroll
        for (int b = 0; b < 8; b++)
#pragma unroll
            for (int c = 0; c < 4; c++) acc[a][b][c] = 0.0f;

    load_w(smc, 0, t);
    load_x(smc, pre + (size_t)bb * CP_ * M_ + tok0, M_, t);
    __syncthreads();
    compute_chunk(smc, wm, wn, lane, acc);
    __syncthreads();
    stage_acc(smc, wm, wn, lane, acc);
    __syncthreads();

    const float* stg = (const float*)(smc + OFF_STAGE);
    const float* zB = g_Z + (size_t)bb * N_ * D_;
    float* ob = out + ((size_t)bb * M_ + tok0) * D_;
    const int g = t & 7, tokl = t >> 3;

    // per-thread folded BN scale/shift for its 16 d's
    float s4[4][4], t4[4][4];
#pragma unroll
    for (int i = 0; i < 4; i++) {
        int d0 = g * 4 + 32 * i;
        float4 rv = *(const float4*)(rvar + d0);
        float4 gm = *(const float4*)(gamma + d0);
        float4 bi = *(const float4*)(bias + d0);
        float4 rm = *(const float4*)(rmean + d0);
        float4 be = *(const float4*)(beta + d0);
        s4[i][0] = rsqrtf(rv.x + 1e-5f) * gm.x;
        s4[i][1] = rsqrtf(rv.y + 1e-5f) * gm.y;
        s4[i][2] = rsqrtf(rv.z + 1e-5f) * gm.z;
        s4[i][3] = rsqrtf(rv.w + 1e-5f) * gm.w;
        t4[i][0] = (bi.x - rm.x) * s4[i][0] + be.x;
        t4[i][1] = (bi.y - rm.y) * s4[i][1] + be.y;
        t4[i][2] = (bi.z - rm.z) * s4[i][2] + be.z;
        t4[i][3] = (bi.w - rm.w) * s4[i][3] + be.w;
    }

#pragma unroll
    for (int p = 0; p < 4; p++) {
        int tok = p * 32 + tokl;
        const float* zr = zB + (size_t)sIdx[tok] * D_;
#pragma unroll
        for (int i = 0; i < 4; i++) {
            int d0 = g * 4 + 32 * i;
            float4 z = *(const float4*)(zr + d0);
            float4 v;
            v.x = fmaxf((stg[(d0 + 0) * SWORDS + tok] + z.x) * s4[i][0] + t4[i][0], 0.0f);
            v.y = fmaxf((stg[(d0 + 1) * SWORDS + tok] + z.y) * s4[i][1] + t4[i][1], 0.0f);
            v.z = fmaxf((stg[(d0 + 2) * SWORDS + tok] + z.z) * s4[i][2] + t4[i][2], 0.0f);
            v.w = fmaxf((stg[(d0 + 3) * SWORDS + tok] + z.w) * s4[i][3] + t4[i][3], 0.0f);
            *(float4*)(ob + (size_t)tok * D_ + d0) = v;
        }
    }
}

extern "C" void kernel_launch(void* const* d_in, const int* in_sizes, int n_in,
                              void* d_out, int out_size) {
    const float* pre_x  = (const float*)d_in[0];
    const float* cur_x  = (const float*)d_in[1];
    const void*  up_idx = d_in[2];
    const float* w      = (const float*)d_in[3];
    const float* bias   = (const float*)d_in[4];
    const float* gamma  = (const float*)d_in[5];
    const float* beta   = (const float*)d_in[6];
    const float* rmean  = (const float*)d_in[7];
    const float* rvar   = (const float*)d_in[8];
    float* out = (float*)d_out;

    cudaFuncSetAttribute(zgemm, cudaFuncAttributeMaxDynamicSharedMemorySize, SMEM_TOTAL);
    cudaFuncSetAttribute(fuse, cudaFuncAttributeMaxDynamicSharedMemorySize, SMEM_TOTAL);

    setup_kernel<<<(CIN * 128 + 255) / 256, 256>>>(w, up_idx);
    zgemm<<<dim3(N_ / 128, B_), 256, SMEM_TOTAL>>>(cur_x);
    fuse<<<dim3(M_ / 128, B_), 256, SMEM_TOTAL>>>(pre_x, up_idx, bias, gamma, beta,
                                                  rmean, rvar, out);
}

// round 4
// speedup vs baseline: 1.9763x; 1.0914x over previous
#include <cuda_runtime.h>
#include <cstdint>

#define B_   4
#define M_   65536
#define N_   16384
#define D_   128
#define CIN  192
#define CP_  64

#define APITCHW 68          // A row pitch words (64 data + 4 pad) = 272B, 16B mult
#define BPITCHW 136         // B row pitch words (128 data + 8 pad) = 544B, 16B mult
#define SWORDS  133         // staging pitch words

#define OFF_A   1024
#define ASZB    (128 * APITCHW * 4)     // 34816
#define OFF_B   (OFF_A + ASZB)          // 35840
#define BSZB    (64 * BPITCHW * 4)      // 34816
#define SMEM_TOTAL (OFF_B + BSZB)       // 70656
#define OFF_STAGE 1024                  // reuse tiles after mainloop

__device__ float g_Z[(size_t)B_ * N_ * D_];     // 32 MB scratch [b][n][d]
__device__ int g_idx_is64;
// w as A operand: [d][k], tf32-rounded fp32, k interleaved (k0,k4,k1,k5,k2,k6,k3,k7 per k8)
__device__ __align__(16) float g_wt[128 * CIN];

// ---------------- helpers ----------------
static __device__ __forceinline__ uint32_t tf32r(float x) {
    uint32_t r;
    asm("cvt.rna.tf32.f32 %0, %1;" : "=r"(r) : "f"(x));
    return r;
}
static __device__ __forceinline__ void mma_tf32(float* c, uint32_t a0, uint32_t a1,
                                                uint32_t a2, uint32_t a3,
                                                uint32_t b0, uint32_t b1) {
    asm volatile(
        "mma.sync.aligned.m16n8k8.row.col.f32.tf32.tf32.f32 "
        "{%0,%1,%2,%3}, {%4,%5,%6,%7}, {%8,%9}, {%0,%1,%2,%3};"
        : "+f"(c[0]), "+f"(c[1]), "+f"(c[2]), "+f"(c[3])
        : "r"(a0), "r"(a1), "r"(a2), "r"(a3), "r"(b0), "r"(b1));
}
#define CP_ASYNC16(dst_u32, src_ptr) \
    asm volatile("cp.async.cg.shared.global [%0], [%1], 16;" :: "r"(dst_u32), "l"(src_ptr))
#define CP_COMMIT() asm volatile("cp.async.commit_group;" ::: "memory")
#define CP_WAIT0()  asm volatile("cp.async.wait_group 0;" ::: "memory")
static __device__ __forceinline__ uint32_t s2u(const void* p) {
    uint32_t a;
    asm("{ .reg .u64 t; cvta.to.shared.u64 t, %1; cvt.u32.u64 %0, t; }" : "=r"(a) : "l"(p));
    return a;
}

// ---------------- setup: w tf32 transpose/interleave + idx dtype probe ----------------
__global__ void setup_kernel(const float* __restrict__ w, const void* __restrict__ idx) {
    if (blockIdx.x == 0 && threadIdx.x == 0) {
        const long long* p = (const long long*)idx;
        int ok = 1;
        for (int i = 0; i < 64; i++) {
            long long v = p[i];
            if (v < 0 || v >= N_) { ok = 0; break; }
        }
        g_idx_is64 = ok;
    }
    int i = blockIdx.x * 256 + threadIdx.x;      // over CIN*128; w is [k][d]
    if (i < CIN * 128) {
        int k = i / 128, d = i % 128;
        int pos = (k >> 3) * 8 + ((k & 3) * 2 + ((k >> 2) & 1));   // k8-interleave
        ((uint32_t*)g_wt)[d * CIN + pos] = tf32r(w[i]);
    }
}

// ---------------- tile loaders ----------------
// A tile: 128 d x 64 k (one K64 chunk) via cp.async, 8 x 16B per thread
static __device__ __forceinline__ void load_A(uint32_t sb, int k0, int t) {
#pragma unroll
    for (int i = 0; i < 8; i++) {
        int c = t + i * 256;                     // 2048 chunks of 16B
        int d = c >> 4, j = c & 15;
        CP_ASYNC16(sb + OFF_A + d * (APITCHW * 4) + j * 16,
                   (const char*)(g_wt + d * CIN + k0) + j * 16);
    }
    CP_COMMIT();
}
// B tile: 64 k x 128 tok fp32 -> tf32(rna), natural [k][tok] layout, STS.128
static __device__ __forceinline__ void load_B(char* smc, const float* __restrict__ src,
                                              size_t stride, int t) {
    const int col = t & 31, r0 = t >> 5;
#pragma unroll
    for (int i = 0; i < 8; i++) {
        int k = r0 + i * 8;
        float4 v = *(const float4*)(src + (size_t)k * stride + col * 4);
        uint4 u = make_uint4(tf32r(v.x), tf32r(v.y), tf32r(v.z), tf32r(v.w));
        *(uint4*)(smc + OFF_B + k * (BPITCHW * 4) + col * 16) = u;
    }
}

// ---------------- mainloop: one K=64 chunk of the 128d x 128tok tile ----------------
static __device__ __forceinline__ void compute_chunk(char* smc, int wm, int wn, int lane,
                                                     float acc[2][8][4]) {
    const int r = lane >> 2, q = lane & 3;
    const char* aBase = smc + OFF_A + (wm * 32 + r) * (APITCHW * 4) + q * 8;
    const char* bCol  = smc + OFF_B + q * (BPITCHW * 4) + (wn * 64 + r) * 4;
#pragma unroll
    for (int ks = 0; ks < 8; ks++) {
        uint2 a02[2], a13[2];
#pragma unroll
        for (int mt = 0; mt < 2; mt++) {
            const char* ap = aBase + mt * 16 * (APITCHW * 4) + ks * 32;
            a02[mt] = *(const uint2*)ap;                         // a0, a2
            a13[mt] = *(const uint2*)(ap + 8 * (APITCHW * 4));   // a1, a3
        }
        const char* bp = bCol + ks * 8 * (BPITCHW * 4);
#pragma unroll
        for (int nt = 0; nt < 8; nt++) {
            uint32_t b0 = *(const uint32_t*)(bp + nt * 32);
            uint32_t b1 = *(const uint32_t*)(bp + 4 * (BPITCHW * 4) + nt * 32);
#pragma unroll
            for (int mt = 0; mt < 2; mt++)
                mma_tf32(acc[mt][nt], a02[mt].x, a13[mt].x, a02[mt].y, a13[mt].y, b0, b1);
        }
    }
}

// stage accumulators to smem [d][tok] (pitch SWORDS) for coalesced gmem stores
static __device__ __forceinline__ void stage_acc(char* smc, int wm, int wn, int lane,
                                                 float acc[2][8][4]) {
    float* stg = (float*)(smc + OFF_STAGE);
    const int r = lane >> 2, q2 = (lane & 3) * 2;
#pragma unroll
    for (int mt = 0; mt < 2; mt++)
#pragma unroll
        for (int nt = 0; nt < 8; nt++) {
            int d0 = wm * 32 + mt * 16 + r;
            int tk = wn * 64 + nt * 8 + q2;
            stg[d0 * SWORDS + tk]           = acc[mt][nt][0];
            stg[d0 * SWORDS + tk + 1]       = acc[mt][nt][1];
            stg[(d0 + 8) * SWORDS + tk]     = acc[mt][nt][2];
            stg[(d0 + 8) * SWORDS + tk + 1] = acc[mt][nt][3];
        }
}

// ---------------- GEMM 1: Z = w_cur^T @ cur_x ----------------
__global__ void __launch_bounds__(256, 2) zgemm(const float* __restrict__ cur) {
    extern __shared__ char smc[];
    uint32_t sb = s2u(smc);
    const int t = threadIdx.x, lane = t & 31, wid = t >> 5;
    const int wm = wid & 3, wn = wid >> 2;
    const int bb = blockIdx.y, tok0 = blockIdx.x * 128;

    float acc[2][8][4];
#pragma unroll
    for (int a = 0; a < 2; a++)
#pragma unroll
        for (int b = 0; b < 8; b++)
#pragma unroll
            for (int c = 0; c < 4; c++) acc[a][b][c] = 0.0f;

    const float* base = cur + (size_t)bb * 128 * N_ + tok0;
#pragma unroll
    for (int c = 0; c < 2; c++) {
        load_A(sb, CP_ + c * 64, t);
        load_B(smc, base + (size_t)c * 64 * N_, N_, t);
        CP_WAIT0();
        __syncthreads();
        compute_chunk(smc, wm, wn, lane, acc);
        __syncthreads();
    }
    stage_acc(smc, wm, wn, lane, acc);
    __syncthreads();

    const float* stg = (const float*)(smc + OFF_STAGE);
    float* zb = g_Z + ((size_t)bb * N_ + tok0) * D_;
    const int g = t & 7, tokl = t >> 3;
#pragma unroll
    for (int p = 0; p < 4; p++) {
        int tok = p * 32 + tokl;
#pragma unroll
        for (int i = 0; i < 4; i++) {
            int d0 = g * 4 + 32 * i;
            float4 v;
            v.x = stg[(d0 + 0) * SWORDS + tok];
            v.y = stg[(d0 + 1) * SWORDS + tok];
            v.z = stg[(d0 + 2) * SWORDS + tok];
            v.w = stg[(d0 + 3) * SWORDS + tok];
            *(float4*)(zb + (size_t)tok * D_ + d0) = v;
        }
    }
}

// ---------------- GEMM 2 + gather + BN + relu ----------------
__global__ void __launch_bounds__(256, 2) fuse(const float* __restrict__ pre,
                                               const void* __restrict__ up_idx,
                                               const float* __restrict__ bias,
                                               const float* __restrict__ gamma,
                                               const float* __restrict__ beta,
                                               const float* __restrict__ rmean,
                                               const float* __restrict__ rvar,
                                               float* __restrict__ out) {
    extern __shared__ char smc[];
    uint32_t sb = s2u(smc);
    const int t = threadIdx.x, lane = t & 31, wid = t >> 5;
    const int wm = wid & 3, wn = wid >> 2;
    const int bb = blockIdx.y, tok0 = blockIdx.x * 128;

    int* sIdx = (int*)smc;                       // [0,512) — below OFF_A, survives
    if (t < 128) {
        size_t ip = (size_t)bb * M_ + tok0 + t;
        sIdx[t] = g_idx_is64 ? (int)((const long long*)up_idx)[ip]
                             : ((const int*)up_idx)[ip];
    }

    float acc[2][8][4];
#pragma unroll
    for (int a = 0; a < 2; a++)
#pragma unroll
        for (int b = 0; b < 8; b++)
#pragma unroll
            for (int c = 0; c < 4; c++) acc[a][b][c] = 0.0f;

    load_A(sb, 0, t);
    load_B(smc, pre + (size_t)bb * CP_ * M_ + tok0, M_, t);
    CP_WAIT0();
    __syncthreads();
    compute_chunk(smc, wm, wn, lane, acc);
    __syncthreads();
    stage_acc(smc, wm, wn, lane, acc);
    __syncthreads();

    const float* stg = (const float*)(smc + OFF_STAGE);
    const float* zB = g_Z + (size_t)bb * N_ * D_;
    float* ob = out + ((size_t)bb * M_ + tok0) * D_;
    const int g = t & 7, tokl = t >> 3;

    float s4[4][4], t4[4][4];
#pragma unroll
    for (int i = 0; i < 4; i++) {
        int d0 = g * 4 + 32 * i;
        float4 rv = *(const float4*)(rvar + d0);
        float4 gm = *(const float4*)(gamma + d0);
        float4 bi = *(const float4*)(bias + d0);
        float4 rm = *(const float4*)(rmean + d0);
        float4 be = *(const float4*)(beta + d0);
        s4[i][0] = rsqrtf(rv.x + 1e-5f) * gm.x;
        s4[i][1] = rsqrtf(rv.y + 1e-5f) * gm.y;
        s4[i][2] = rsqrtf(rv.z + 1e-5f) * gm.z;
        s4[i][3] = rsqrtf(rv.w + 1e-5f) * gm.w;
        t4[i][0] = (bi.x - rm.x) * s4[i][0] + be.x;
        t4[i][1] = (bi.y - rm.y) * s4[i][1] + be.y;
        t4[i][2] = (bi.z - rm.z) * s4[i][2] + be.z;
        t4[i][3] = (bi.w - rm.w) * s4[i][3] + be.w;
    }

#pragma unroll
    for (int p = 0; p < 4; p++) {
        int tok = p * 32 + tokl;
        const float* zr = zB + (size_t)sIdx[tok] * D_;
#pragma unroll
        for (int i = 0; i < 4; i++) {
            int d0 = g * 4 + 32 * i;
            float4 z = *(const float4*)(zr + d0);
            float4 v;
            v.x = fmaxf((stg[(d0 + 0) * SWORDS + tok] + z.x) * s4[i][0] + t4[i][0], 0.0f);
            v.y = fmaxf((stg[(d0 + 1) * SWORDS + tok] + z.y) * s4[i][1] + t4[i][1], 0.0f);
            v.z = fmaxf((stg[(d0 + 2) * SWORDS + tok] + z.z) * s4[i][2] + t4[i][2], 0.0f);
            v.w = fmaxf((stg[(d0 + 3) * SWORDS + tok] + z.w) * s4[i][3] + t4[i][3], 0.0f);
            *(float4*)(ob + (size_t)tok * D_ + d0) = v;
        }
    }
}

extern "C" void kernel_launch(void* const* d_in, const int* in_sizes, int n_in,
                              void* d_out, int out_size) {
    const float* pre_x  = (const float*)d_in[0];
    const float* cur_x  = (const float*)d_in[1];
    const void*  up_idx = d_in[2];
    const float* w      = (const float*)d_in[3];
    const float* bias   = (const float*)d_in[4];
    const float* gamma  = (const float*)d_in[5];
    const float* beta   = (const float*)d_in[6];
    const float* rmean  = (const float*)d_in[7];
    const float* rvar   = (const float*)d_in[8];
    float* out = (float*)d_out;

    cudaFuncSetAttribute(zgemm, cudaFuncAttributeMaxDynamicSharedMemorySize, SMEM_TOTAL);
    cudaFuncSetAttribute(fuse, cudaFuncAttributeMaxDynamicSharedMemorySize, SMEM_TOTAL);

    setup_kernel<<<(CIN * 128 + 255) / 256, 256>>>(w, up_idx);
    zgemm<<<dim3(N_ / 128, B_), 256, SMEM_TOTAL>>>(cur_x);
    fuse<<<dim3(M_ / 128, B_), 256, SMEM_TOTAL>>>(pre_x, up_idx, bias, gamma, beta,
                                                  rmean, rvar, out);
}